// round 14
// baseline (speedup 1.0000x reference)
#include <cuda_runtime.h>

#define N_NODE 50000
#define N_EDGE 800000
#define HID 128
#define ZD 128
#define ED 64
#define N_ROWS (N_NODE * 4)   // 200000 (node, orb) rows

// ---------------- scratch (device globals: no allocation allowed) ----------------
__device__ float g_AB[N_NODE * 256];         // [node][0:128]=A, [128:256]=B   (51.2 MB)
__device__ float g_E2[N_ROWS * HID];         // e-branch output per (node,orb) (102.4 MB)
__device__ float g_W1T[128 * 256];           // Weff[k][c]
__device__ float g_W2T[128 * 128];           // zW2[n][k] -> [k][n]
__device__ float g_We1T[64 * 128];           // eW1[n][k] -> [k][n]
__device__ float g_We2T[128 * 128];          // eW2[n][k] -> [k][n]

__device__ __forceinline__ float silu_f(float x) {
    return x * __fdividef(1.0f, 1.0f + __expf(-x));
}

// ---------------- kernel 0: weight transposes ----------------
__global__ void prep_kernel(const float* __restrict__ zW1,
                            const float* __restrict__ zW2,
                            const float* __restrict__ eW1,
                            const float* __restrict__ eW2) {
    int i = blockIdx.x * blockDim.x + threadIdx.x;
    if (i < 32768) {                       // g_W1T: 128 k x 256 c
        int k = i >> 8, c = i & 255;
        g_W1T[i] = (c < 128) ? zW1[c * 256 + k] : zW1[(c - 128) * 256 + 128 + k];
    } else if (i < 49152) {                // g_W2T
        int q = i - 32768; int k = q >> 7, n = q & 127;
        g_W2T[q] = zW2[n * 128 + k];
    } else if (i < 57344) {                // g_We1T (64 k x 128 n)
        int q = i - 49152; int k = q >> 7, n = q & 127;
        g_We1T[q] = eW1[n * 64 + k];
    } else if (i < 73728) {                // g_We2T
        int q = i - 57344; int k = q >> 7, n = q & 127;
        g_We2T[q] = eW2[n * 128 + k];
    }
}

// ---------------- kernel 1: per-node A|B = silu(z) @ W1eff^T ----------------
// grid (391, 2) ; block 256 ; tile: 128 nodes x 128 cols, K=128 (weights chunked by 64)
__global__ __launch_bounds__(256, 2)
void nodeAB_kernel(const float* __restrict__ z_embed) {
    extern __shared__ float sm[];
    float* sP = sm;            // [128][128]  silu(z) tile (row-major, ld=128)
    float* sW = sm + 16384;    // [64][132]   weight K-chunk, [k][n], ld=132
    const int tid = threadIdx.x;
    const int m0 = blockIdx.x * 128;
    const int half = blockIdx.y;

    #pragma unroll
    for (int it = 0; it < 16; ++it) {
        int m = it * 8 + (tid >> 5);
        int k4 = (tid & 31) * 4;
        int node = m0 + m;
        float4 v = make_float4(0.f, 0.f, 0.f, 0.f);
        if (node < N_NODE) v = *reinterpret_cast<const float4*>(&z_embed[node * ZD + k4]);
        v.x = silu_f(v.x); v.y = silu_f(v.y); v.z = silu_f(v.z); v.w = silu_f(v.w);
        *reinterpret_cast<float4*>(&sP[m * 128 + k4]) = v;
    }

    const int ty = tid >> 4, tx = tid & 15;
    const int mB = ty * 8, nB = tx * 8;
    float acc[8][8];
    #pragma unroll
    for (int r = 0; r < 8; ++r)
        #pragma unroll
        for (int c = 0; c < 8; ++c) acc[r][c] = 0.f;

    for (int c64 = 0; c64 < 2; ++c64) {
        if (c64) __syncthreads();
        #pragma unroll
        for (int it = 0; it < 8; ++it) {
            int kr = it * 8 + (tid >> 5);
            int n4 = (tid & 31) * 4;
            float4 w = *reinterpret_cast<const float4*>(
                &g_W1T[(c64 * 64 + kr) * 256 + half * 128 + n4]);
            *reinterpret_cast<float4*>(&sW[kr * 132 + n4]) = w;
        }
        __syncthreads();
        #pragma unroll 4
        for (int k = 0; k < 64; ++k) {
            float a[8], b[8];
            #pragma unroll
            for (int r = 0; r < 8; ++r) a[r] = sP[(mB + r) * 128 + c64 * 64 + k];
            float4 b0 = *reinterpret_cast<const float4*>(&sW[k * 132 + nB]);
            float4 b1 = *reinterpret_cast<const float4*>(&sW[k * 132 + nB + 4]);
            b[0]=b0.x; b[1]=b0.y; b[2]=b0.z; b[3]=b0.w;
            b[4]=b1.x; b[5]=b1.y; b[6]=b1.z; b[7]=b1.w;
            #pragma unroll
            for (int r = 0; r < 8; ++r)
                #pragma unroll
                for (int c = 0; c < 8; ++c) acc[r][c] = fmaf(a[r], b[c], acc[r][c]);
        }
    }

    #pragma unroll
    for (int r = 0; r < 8; ++r) {
        int node = m0 + mB + r;
        if (node < N_NODE) {
            #pragma unroll
            for (int c = 0; c < 8; c += 4) {
                float4 o = make_float4(acc[r][c], acc[r][c+1], acc[r][c+2], acc[r][c+3]);
                *reinterpret_cast<float4*>(&g_AB[node * 256 + half * 128 + nB + c]) = o;
            }
        }
    }
}

// ---------------- kernel 2: per-(node,orb) e-branch, fused 2 layers ----------------
// grid 1563 ; block 256 ; tile: 128 rows x 128, K1=64, K2=128
__global__ __launch_bounds__(256, 1)
void nodeE_kernel(const float* __restrict__ e_embed) {
    extern __shared__ float sm[];
    float* sX  = sm;            // [128][64]
    float* sW1 = sm + 8192;     // [64][132]
    float* sH  = sm + 16640;    // [128][128]
    float* sW2 = sm + 33024;    // [128][132]
    const int tid = threadIdx.x;
    const int r0 = blockIdx.x * 128;

    #pragma unroll
    for (int it = 0; it < 8; ++it) {                // silu(e_embed) tile
        int m = it * 16 + (tid >> 4);
        int k4 = (tid & 15) * 4;
        int row = r0 + m;
        float4 v = make_float4(0.f, 0.f, 0.f, 0.f);
        if (row < N_ROWS) v = *reinterpret_cast<const float4*>(&e_embed[row * ED + k4]);
        v.x = silu_f(v.x); v.y = silu_f(v.y); v.z = silu_f(v.z); v.w = silu_f(v.w);
        *reinterpret_cast<float4*>(&sX[m * 64 + k4]) = v;
    }
    #pragma unroll
    for (int it = 0; it < 8; ++it) {                // W1 [k][n]
        int kr = it * 8 + (tid >> 5);
        int n4 = (tid & 31) * 4;
        float4 w = *reinterpret_cast<const float4*>(&g_We1T[kr * 128 + n4]);
        *reinterpret_cast<float4*>(&sW1[kr * 132 + n4]) = w;
    }
    #pragma unroll
    for (int it = 0; it < 16; ++it) {               // W2 [k][n]
        int kr = it * 8 + (tid >> 5);
        int n4 = (tid & 31) * 4;
        float4 w = *reinterpret_cast<const float4*>(&g_We2T[kr * 128 + n4]);
        *reinterpret_cast<float4*>(&sW2[kr * 132 + n4]) = w;
    }
    __syncthreads();

    const int ty = tid >> 4, tx = tid & 15;
    const int mB = ty * 8, nB = tx * 8;
    float acc[8][8];
    #pragma unroll
    for (int r = 0; r < 8; ++r)
        #pragma unroll
        for (int c = 0; c < 8; ++c) acc[r][c] = 0.f;

    #pragma unroll 4
    for (int k = 0; k < 64; ++k) {                  // layer 1
        float a[8], b[8];
        #pragma unroll
        for (int r = 0; r < 8; ++r) a[r] = sX[(mB + r) * 64 + k];
        float4 b0 = *reinterpret_cast<const float4*>(&sW1[k * 132 + nB]);
        float4 b1 = *reinterpret_cast<const float4*>(&sW1[k * 132 + nB + 4]);
        b[0]=b0.x; b[1]=b0.y; b[2]=b0.z; b[3]=b0.w;
        b[4]=b1.x; b[5]=b1.y; b[6]=b1.z; b[7]=b1.w;
        #pragma unroll
        for (int r = 0; r < 8; ++r)
            #pragma unroll
            for (int c = 0; c < 8; ++c) acc[r][c] = fmaf(a[r], b[c], acc[r][c]);
    }

    #pragma unroll
    for (int r = 0; r < 8; ++r) {                   // sH = silu(layer1)
        #pragma unroll
        for (int c = 0; c < 8; c += 4) {
            float4 h;
            h.x = silu_f(acc[r][c]);   h.y = silu_f(acc[r][c+1]);
            h.z = silu_f(acc[r][c+2]); h.w = silu_f(acc[r][c+3]);
            *reinterpret_cast<float4*>(&sH[(mB + r) * 128 + nB + c]) = h;
        }
    }
    __syncthreads();

    float acc2[8][8];
    #pragma unroll
    for (int r = 0; r < 8; ++r)
        #pragma unroll
        for (int c = 0; c < 8; ++c) acc2[r][c] = 0.f;

    #pragma unroll 4
    for (int k = 0; k < 128; ++k) {                 // layer 2
        float a[8], b[8];
        #pragma unroll
        for (int r = 0; r < 8; ++r) a[r] = sH[(mB + r) * 128 + k];
        float4 b0 = *reinterpret_cast<const float4*>(&sW2[k * 132 + nB]);
        float4 b1 = *reinterpret_cast<const float4*>(&sW2[k * 132 + nB + 4]);
        b[0]=b0.x; b[1]=b0.y; b[2]=b0.z; b[3]=b0.w;
        b[4]=b1.x; b[5]=b1.y; b[6]=b1.z; b[7]=b1.w;
        #pragma unroll
        for (int r = 0; r < 8; ++r)
            #pragma unroll
            for (int c = 0; c < 8; ++c) acc2[r][c] = fmaf(a[r], b[c], acc2[r][c]);
    }

    #pragma unroll
    for (int r = 0; r < 8; ++r) {
        int row = r0 + mB + r;
        if (row < N_ROWS) {
            #pragma unroll
            for (int c = 0; c < 8; c += 4) {
                float4 o = make_float4(acc2[r][c], acc2[r][c+1], acc2[r][c+2], acc2[r][c+3]);
                *reinterpret_cast<float4*>(&g_E2[row * 128 + nB + c]) = o;
            }
        }
    }
}

// ---------------- kernel 3: per-edge second layer + epilogue ----------------
// grid 6250 ; block 256 ; tile: 128 edges x 128 hid, K=128 (weights chunked by 64)
__global__ __launch_bounds__(256, 2)
void edge_kernel(const int* __restrict__ idx_i, const int* __restrict__ idx_j,
                 const float* __restrict__ zb1, const float* __restrict__ zb2,
                 float* __restrict__ out) {
    extern __shared__ float sm[];
    float* sS  = sm;            // [128][128]  s = silu(A[i]+B[j]+zb1) ; later reused as g
    float* sW  = sm + 16384;    // [64][132] -> ends at 24832
    float* sB2 = sm + 24832;    // [128]     -> ends at 24960
    int*   sJ  = reinterpret_cast<int*>(sm + 24960);  // [128] -> ends at 25088 (= alloc)
    const int tid = threadIdx.x;
    const int e0 = blockIdx.x * 128;

    if (tid < 128) {
        sB2[tid] = zb2[tid];
        sJ[tid] = idx_j[e0 + tid];
    }

    // build s tile
    #pragma unroll
    for (int it = 0; it < 16; ++it) {
        int m = it * 8 + (tid >> 5);
        int k4 = (tid & 31) * 4;
        int e = e0 + m;
        int i = __ldg(&idx_i[e]);
        int j = __ldg(&idx_j[e]);
        float4 a = *reinterpret_cast<const float4*>(&g_AB[i * 256 + k4]);
        float4 b = *reinterpret_cast<const float4*>(&g_AB[j * 256 + 128 + k4]);
        float4 bias = __ldg(reinterpret_cast<const float4*>(&zb1[k4]));
        float4 s;
        s.x = silu_f(a.x + b.x + bias.x);
        s.y = silu_f(a.y + b.y + bias.y);
        s.z = silu_f(a.z + b.z + bias.z);
        s.w = silu_f(a.w + b.w + bias.w);
        *reinterpret_cast<float4*>(&sS[m * 128 + k4]) = s;
    }

    const int ty = tid >> 4, tx = tid & 15;
    const int mB = ty * 8, nB = tx * 8;
    float acc[8][8];
    #pragma unroll
    for (int r = 0; r < 8; ++r)
        #pragma unroll
        for (int c = 0; c < 8; ++c) acc[r][c] = 0.f;

    for (int c64 = 0; c64 < 2; ++c64) {
        if (c64) __syncthreads();
        #pragma unroll
        for (int it = 0; it < 8; ++it) {
            int kr = it * 8 + (tid >> 5);
            int n4 = (tid & 31) * 4;
            float4 w = *reinterpret_cast<const float4*>(&g_W2T[(c64 * 64 + kr) * 128 + n4]);
            *reinterpret_cast<float4*>(&sW[kr * 132 + n4]) = w;
        }
        __syncthreads();
        #pragma unroll 4
        for (int k = 0; k < 64; ++k) {
            float a[8], b[8];
            #pragma unroll
            for (int r = 0; r < 8; ++r) a[r] = sS[(mB + r) * 128 + c64 * 64 + k];
            float4 b0 = *reinterpret_cast<const float4*>(&sW[k * 132 + nB]);
            float4 b1 = *reinterpret_cast<const float4*>(&sW[k * 132 + nB + 4]);
            b[0]=b0.x; b[1]=b0.y; b[2]=b0.z; b[3]=b0.w;
            b[4]=b1.x; b[5]=b1.y; b[6]=b1.z; b[7]=b1.w;
            #pragma unroll
            for (int r = 0; r < 8; ++r)
                #pragma unroll
                for (int c = 0; c < 8; ++c) acc[r][c] = fmaf(a[r], b[c], acc[r][c]);
        }
    }
    __syncthreads();    // everyone done reading sS -> safe to overwrite with g

    // g = 1 + z2 = 1 + acc + zb2
    #pragma unroll
    for (int r = 0; r < 8; ++r) {
        #pragma unroll
        for (int c = 0; c < 8; c += 4) {
            float4 g;
            g.x = 1.f + acc[r][c]   + sB2[nB + c];
            g.y = 1.f + acc[r][c+1] + sB2[nB + c + 1];
            g.z = 1.f + acc[r][c+2] + sB2[nB + c + 2];
            g.w = 1.f + acc[r][c+3] + sB2[nB + c + 3];
            *reinterpret_cast<float4*>(&sS[(mB + r) * 128 + nB + c]) = g;
        }
    }
    __syncthreads();

    // epilogue: out[e, orb, h] = E2[j, orb, h] * g[e, h]
    const int h = (tid & 31) * 4;
    const int orb = (tid >> 5) & 3;
    #pragma unroll 4
    for (int it = 0; it < 64; ++it) {
        int m = it * 2 + (tid >> 7);
        int j = sJ[m];
        float4 ev = *reinterpret_cast<const float4*>(&g_E2[(j * 4 + orb) * 128 + h]);
        float4 g  = *reinterpret_cast<const float4*>(&sS[m * 128 + h]);
        float4 o;
        o.x = ev.x * g.x; o.y = ev.y * g.y; o.z = ev.z * g.z; o.w = ev.w * g.w;
        size_t off = ((size_t)(e0 + m) * 4 + orb) * 128 + h;
        __stcs(reinterpret_cast<float4*>(&out[off]), o);   // streaming: keep E2 in L2
    }
}

// ---------------- launch ----------------
extern "C" void kernel_launch(void* const* d_in, const int* in_sizes, int n_in,
                              void* d_out, int out_size) {
    const float* z_embed = (const float*)d_in[0];
    const float* e_embed = (const float*)d_in[1];
    const int*   idx_i   = (const int*)d_in[2];
    const int*   idx_j   = (const int*)d_in[3];
    const float* zW1     = (const float*)d_in[4];
    const float* zb1     = (const float*)d_in[5];
    const float* zW2     = (const float*)d_in[6];
    const float* zb2     = (const float*)d_in[7];
    const float* eW1     = (const float*)d_in[8];
    const float* eW2     = (const float*)d_in[9];
    float* out = (float*)d_out;

    const int SMEM1 = (16384 + 64 * 132) * 4;                    //  99328 B
    const int SMEM2 = (8192 + 64 * 132 + 16384 + 128 * 132) * 4; // 199680 B
    const int SMEM3 = (16384 + 64 * 132 + 128 + 128) * 4;        // 100352 B
    cudaFuncSetAttribute(nodeAB_kernel, cudaFuncAttributeMaxDynamicSharedMemorySize, SMEM1);
    cudaFuncSetAttribute(nodeE_kernel,  cudaFuncAttributeMaxDynamicSharedMemorySize, SMEM2);
    cudaFuncSetAttribute(edge_kernel,   cudaFuncAttributeMaxDynamicSharedMemorySize, SMEM3);

    prep_kernel<<<288, 256>>>(zW1, zW2, eW1, eW2);
    nodeAB_kernel<<<dim3(391, 2), 256, SMEM1>>>(z_embed);
    nodeE_kernel<<<1563, 256, SMEM2>>>(e_embed);
    edge_kernel<<<6250, 256, SMEM3>>>(idx_i, idx_j, zb1, zb2, out);
}

// round 15
// speedup vs baseline: 1.0942x; 1.0942x over previous
#include <cuda_runtime.h>

#define N_NODE 50000
#define N_EDGE 800000
#define HID 128
#define ZD 128
#define ED 64
#define N_ROWS (N_NODE * 4)   // 200000 (node, orb) rows

// ---------------- scratch (device globals: no allocation allowed) ----------------
__device__ float g_AB[N_NODE * 256];         // [node][0:128]=A, [128:256]=B
__device__ float g_E2[N_ROWS * HID];         // e-branch output per (node,orb)
__device__ float g_W1T[128 * 256];           // Weff[k][c]
__device__ float g_W2T[128 * 128];           // zW2[n][k] -> [k][n]
__device__ float g_We1T[64 * 128];           // eW1[n][k] -> [k][n]
__device__ float g_We2T[128 * 128];          // eW2[n][k] -> [k][n]

__device__ __forceinline__ float silu_f(float x) {
    return x * __fdividef(1.0f, 1.0f + __expf(-x));
}

// ---------------- kernel 0: weight transposes ----------------
__global__ void prep_kernel(const float* __restrict__ zW1,
                            const float* __restrict__ zW2,
                            const float* __restrict__ eW1,
                            const float* __restrict__ eW2) {
    int i = blockIdx.x * blockDim.x + threadIdx.x;
    if (i < 32768) {                       // g_W1T: 128 k x 256 c
        int k = i >> 8, c = i & 255;
        g_W1T[i] = (c < 128) ? zW1[c * 256 + k] : zW1[(c - 128) * 256 + 128 + k];
    } else if (i < 49152) {                // g_W2T
        int q = i - 32768; int k = q >> 7, n = q & 127;
        g_W2T[q] = zW2[n * 128 + k];
    } else if (i < 57344) {                // g_We1T (64 k x 128 n)
        int q = i - 49152; int k = q >> 7, n = q & 127;
        g_We1T[q] = eW1[n * 64 + k];
    } else if (i < 73728) {                // g_We2T
        int q = i - 57344; int k = q >> 7, n = q & 127;
        g_We2T[q] = eW2[n * 128 + k];
    }
}

// 8x4 inner product step: a broadcast via LDS.32, b via one LDS.128
#define STEP84(SPTR, SLD, KIDX, SW, KW, ACC)                                    \
    {                                                                           \
        float a[8];                                                             \
        _Pragma("unroll")                                                       \
        for (int r = 0; r < 8; ++r) a[r] = (SPTR)[(mB + r) * (SLD) + (KIDX)];   \
        float4 b0 = *reinterpret_cast<const float4*>(&(SW)[(KW) * 132 + nB]);   \
        _Pragma("unroll")                                                       \
        for (int r = 0; r < 8; ++r) {                                           \
            ACC[r][0] = fmaf(a[r], b0.x, ACC[r][0]);                            \
            ACC[r][1] = fmaf(a[r], b0.y, ACC[r][1]);                            \
            ACC[r][2] = fmaf(a[r], b0.z, ACC[r][2]);                            \
            ACC[r][3] = fmaf(a[r], b0.w, ACC[r][3]);                            \
        }                                                                       \
    }

// ---------------- kernel 1: per-node A|B = silu(z) @ W1eff^T ----------------
// grid (391, 2) ; block 512 ; tile 128 nodes x 128 cols ; per-thread 8x4
__global__ __launch_bounds__(512, 2)
void nodeAB_kernel(const float* __restrict__ z_embed) {
    extern __shared__ float sm[];
    float* sP = sm;            // [128][128]
    float* sW = sm + 16384;    // [64][132]
    const int tid = threadIdx.x;
    const int m0 = blockIdx.x * 128;
    const int half = blockIdx.y;

    #pragma unroll
    for (int it = 0; it < 8; ++it) {
        int m = it * 16 + (tid >> 5);
        int k4 = (tid & 31) * 4;
        int node = m0 + m;
        float4 v = make_float4(0.f, 0.f, 0.f, 0.f);
        if (node < N_NODE) v = *reinterpret_cast<const float4*>(&z_embed[node * ZD + k4]);
        v.x = silu_f(v.x); v.y = silu_f(v.y); v.z = silu_f(v.z); v.w = silu_f(v.w);
        *reinterpret_cast<float4*>(&sP[m * 128 + k4]) = v;
    }

    const int mB = (tid >> 5) * 8;
    const int nB = (tid & 31) * 4;
    float acc[8][4];
    #pragma unroll
    for (int r = 0; r < 8; ++r)
        #pragma unroll
        for (int c = 0; c < 4; ++c) acc[r][c] = 0.f;

    for (int c64 = 0; c64 < 2; ++c64) {
        if (c64) __syncthreads();
        #pragma unroll
        for (int it = 0; it < 4; ++it) {
            int kr = it * 16 + (tid >> 5);
            int n4 = (tid & 31) * 4;
            float4 w = *reinterpret_cast<const float4*>(
                &g_W1T[(c64 * 64 + kr) * 256 + half * 128 + n4]);
            *reinterpret_cast<float4*>(&sW[kr * 132 + n4]) = w;
        }
        __syncthreads();
        #pragma unroll 4
        for (int k = 0; k < 64; ++k)
            STEP84(sP, 128, c64 * 64 + k, sW, k, acc)
    }

    #pragma unroll
    for (int r = 0; r < 8; ++r) {
        int node = m0 + mB + r;
        if (node < N_NODE) {
            float4 o = make_float4(acc[r][0], acc[r][1], acc[r][2], acc[r][3]);
            *reinterpret_cast<float4*>(&g_AB[node * 256 + half * 128 + nB]) = o;
        }
    }
}

// ---------------- kernel 2: per-(node,orb) e-branch, fused 2 layers ----------------
// grid 1563 ; block 512 ; tile 128 rows x 128 ; per-thread 8x4
__global__ __launch_bounds__(512, 1)
void nodeE_kernel(const float* __restrict__ e_embed) {
    extern __shared__ float sm[];
    float* sX  = sm;            // [128][64]
    float* sW1 = sm + 8192;     // [64][132]
    float* sH  = sm + 16640;    // [128][128]
    float* sW2 = sm + 33024;    // [128][132]
    const int tid = threadIdx.x;
    const int r0 = blockIdx.x * 128;

    #pragma unroll
    for (int it = 0; it < 4; ++it) {                // silu(e_embed) tile
        int m = it * 32 + (tid >> 4);
        int k4 = (tid & 15) * 4;
        int row = r0 + m;
        float4 v = make_float4(0.f, 0.f, 0.f, 0.f);
        if (row < N_ROWS) v = *reinterpret_cast<const float4*>(&e_embed[row * ED + k4]);
        v.x = silu_f(v.x); v.y = silu_f(v.y); v.z = silu_f(v.z); v.w = silu_f(v.w);
        *reinterpret_cast<float4*>(&sX[m * 64 + k4]) = v;
    }
    #pragma unroll
    for (int it = 0; it < 4; ++it) {                // W1 [k][n]
        int kr = it * 16 + (tid >> 5);
        int n4 = (tid & 31) * 4;
        float4 w = *reinterpret_cast<const float4*>(&g_We1T[kr * 128 + n4]);
        *reinterpret_cast<float4*>(&sW1[kr * 132 + n4]) = w;
    }
    #pragma unroll
    for (int it = 0; it < 8; ++it) {                // W2 [k][n]
        int kr = it * 16 + (tid >> 5);
        int n4 = (tid & 31) * 4;
        float4 w = *reinterpret_cast<const float4*>(&g_We2T[kr * 128 + n4]);
        *reinterpret_cast<float4*>(&sW2[kr * 132 + n4]) = w;
    }
    __syncthreads();

    const int mB = (tid >> 5) * 8;
    const int nB = (tid & 31) * 4;
    float acc[8][4];
    #pragma unroll
    for (int r = 0; r < 8; ++r)
        #pragma unroll
        for (int c = 0; c < 4; ++c) acc[r][c] = 0.f;

    #pragma unroll 4
    for (int k = 0; k < 64; ++k)                    // layer 1
        STEP84(sX, 64, k, sW1, k, acc)

    #pragma unroll
    for (int r = 0; r < 8; ++r) {                   // sH = silu(layer1)
        float4 h;
        h.x = silu_f(acc[r][0]); h.y = silu_f(acc[r][1]);
        h.z = silu_f(acc[r][2]); h.w = silu_f(acc[r][3]);
        *reinterpret_cast<float4*>(&sH[(mB + r) * 128 + nB]) = h;
    }
    __syncthreads();

    float acc2[8][4];
    #pragma unroll
    for (int r = 0; r < 8; ++r)
        #pragma unroll
        for (int c = 0; c < 4; ++c) acc2[r][c] = 0.f;

    #pragma unroll 4
    for (int k = 0; k < 128; ++k)                   // layer 2
        STEP84(sH, 128, k, sW2, k, acc2)

    #pragma unroll
    for (int r = 0; r < 8; ++r) {
        int row = r0 + mB + r;
        if (row < N_ROWS) {
            float4 o = make_float4(acc2[r][0], acc2[r][1], acc2[r][2], acc2[r][3]);
            *reinterpret_cast<float4*>(&g_E2[row * 128 + nB]) = o;
        }
    }
}

// ---------------- kernel 3: per-edge second layer + epilogue ----------------
// grid 6250 ; block 512 ; tile 128 edges x 128 hid ; per-thread 8x4
__global__ __launch_bounds__(512, 2)
void edge_kernel(const int* __restrict__ idx_i, const int* __restrict__ idx_j,
                 const float* __restrict__ zb1, const float* __restrict__ zb2,
                 float* __restrict__ out) {
    extern __shared__ float sm[];
    float* sS  = sm;            // [128][128]  s tile; later reused as g
    float* sW  = sm + 16384;    // [64][132] -> ends 24832
    float* sB2 = sm + 24832;    // [128]
    int*   sJ  = reinterpret_cast<int*>(sm + 24960);  // [128] -> ends 25088 (= alloc)
    const int tid = threadIdx.x;
    const int e0 = blockIdx.x * 128;

    if (tid < 128) {
        sB2[tid] = zb2[tid];
        sJ[tid] = idx_j[e0 + tid];
    }

    // build s tile
    #pragma unroll
    for (int it = 0; it < 8; ++it) {
        int m = it * 16 + (tid >> 5);
        int k4 = (tid & 31) * 4;
        int e = e0 + m;
        int i = __ldg(&idx_i[e]);
        int j = __ldg(&idx_j[e]);
        float4 a = *reinterpret_cast<const float4*>(&g_AB[i * 256 + k4]);
        float4 b = *reinterpret_cast<const float4*>(&g_AB[j * 256 + 128 + k4]);
        float4 bias = __ldg(reinterpret_cast<const float4*>(&zb1[k4]));
        float4 s;
        s.x = silu_f(a.x + b.x + bias.x);
        s.y = silu_f(a.y + b.y + bias.y);
        s.z = silu_f(a.z + b.z + bias.z);
        s.w = silu_f(a.w + b.w + bias.w);
        *reinterpret_cast<float4*>(&sS[m * 128 + k4]) = s;
    }

    const int mB = (tid >> 5) * 8;
    const int nB = (tid & 31) * 4;
    float acc[8][4];
    #pragma unroll
    for (int r = 0; r < 8; ++r)
        #pragma unroll
        for (int c = 0; c < 4; ++c) acc[r][c] = 0.f;

    for (int c64 = 0; c64 < 2; ++c64) {
        if (c64) __syncthreads();
        #pragma unroll
        for (int it = 0; it < 4; ++it) {
            int kr = it * 16 + (tid >> 5);
            int n4 = (tid & 31) * 4;
            float4 w = *reinterpret_cast<const float4*>(&g_W2T[(c64 * 64 + kr) * 128 + n4]);
            *reinterpret_cast<float4*>(&sW[kr * 132 + n4]) = w;
        }
        __syncthreads();
        #pragma unroll 4
        for (int k = 0; k < 64; ++k)
            STEP84(sS, 128, c64 * 64 + k, sW, k, acc)
    }
    __syncthreads();    // done reading sS -> safe to overwrite with g

    // g = 1 + z2 + zb2
    #pragma unroll
    for (int r = 0; r < 8; ++r) {
        float4 g;
        g.x = 1.f + acc[r][0] + sB2[nB + 0];
        g.y = 1.f + acc[r][1] + sB2[nB + 1];
        g.z = 1.f + acc[r][2] + sB2[nB + 2];
        g.w = 1.f + acc[r][3] + sB2[nB + 3];
        *reinterpret_cast<float4*>(&sS[(mB + r) * 128 + nB]) = g;
    }
    __syncthreads();

    // epilogue: out[e, orb, h] = E2[j, orb, h] * g[e, h]
    const int h = (tid & 31) * 4;
    const int orb = (tid >> 5) & 3;
    const int msel = tid >> 7;            // 0..3
    #pragma unroll 4
    for (int it = 0; it < 32; ++it) {
        int m = it * 4 + msel;
        int j = sJ[m];
        float4 ev = *reinterpret_cast<const float4*>(&g_E2[(j * 4 + orb) * 128 + h]);
        float4 g  = *reinterpret_cast<const float4*>(&sS[m * 128 + h]);
        float4 o;
        o.x = ev.x * g.x; o.y = ev.y * g.y; o.z = ev.z * g.z; o.w = ev.w * g.w;
        size_t off = ((size_t)(e0 + m) * 4 + orb) * 128 + h;
        __stcs(reinterpret_cast<float4*>(&out[off]), o);   // streaming: keep E2 in L2
    }
}

// ---------------- launch ----------------
extern "C" void kernel_launch(void* const* d_in, const int* in_sizes, int n_in,
                              void* d_out, int out_size) {
    const float* z_embed = (const float*)d_in[0];
    const float* e_embed = (const float*)d_in[1];
    const int*   idx_i   = (const int*)d_in[2];
    const int*   idx_j   = (const int*)d_in[3];
    const float* zW1     = (const float*)d_in[4];
    const float* zb1     = (const float*)d_in[5];
    const float* zW2     = (const float*)d_in[6];
    const float* zb2     = (const float*)d_in[7];
    const float* eW1     = (const float*)d_in[8];
    const float* eW2     = (const float*)d_in[9];
    float* out = (float*)d_out;

    const int SMEM1 = (16384 + 64 * 132) * 4;                    //  99328 B
    const int SMEM2 = (8192 + 64 * 132 + 16384 + 128 * 132) * 4; // 199680 B
    const int SMEM3 = (16384 + 64 * 132 + 128 + 128) * 4;        // 100352 B
    cudaFuncSetAttribute(nodeAB_kernel, cudaFuncAttributeMaxDynamicSharedMemorySize, SMEM1);
    cudaFuncSetAttribute(nodeE_kernel,  cudaFuncAttributeMaxDynamicSharedMemorySize, SMEM2);
    cudaFuncSetAttribute(edge_kernel,   cudaFuncAttributeMaxDynamicSharedMemorySize, SMEM3);

    prep_kernel<<<288, 256>>>(zW1, zW2, eW1, eW2);
    nodeAB_kernel<<<dim3(391, 2), 512, SMEM1>>>(z_embed);
    nodeE_kernel<<<1563, 512, SMEM2>>>(e_embed);
    edge_kernel<<<6250, 512, SMEM3>>>(idx_i, idx_j, zb1, zb2, out);
}